// round 11
// baseline (speedup 1.0000x reference)
#include <cuda_runtime.h>
#include <cuda_bf16.h>
#include <math.h>
#include <stdint.h>

// Problem constants
#define NB   256
#define NS   1024
#define NROWS (NB * NS)   // 262144

// Scratch (device globals; padded for branch-free depth-4 prefetch)
__device__ float g_u[(size_t)NROWS * 128 + 512];
__device__ float g_bx[(size_t)NROWS * 8 + 32];
// bf16 weight images, transposed to [n][k], row stride 136 elements
__device__ __nv_bfloat16 g_B1h[17408], g_B1l[17408], g_B2h[17408];
// producer->consumer progress flags: g_flag[b*8 + k] = tile (batch b, s-chunk k) done
__device__ int g_flag[2048];

// ---------------- math helpers ----------------
__device__ __forceinline__ float gelu_exact(float x) {
    return 0.5f * x * (1.0f + erff(x * 0.7071067811865475f));
}
__device__ __forceinline__ float sigmoidf_(float v) { return 1.0f / (1.0f + expf(-v)); }
__device__ __forceinline__ float tanh_fast(float x) {
    float y; asm("tanh.approx.f32 %0, %1;" : "=f"(y) : "f"(x)); return y;
}
__device__ __forceinline__ float gelu_fast(float x) {
    float x2 = x * x;
    float inner = 0.7978845608f * x * fmaf(0.044715f, x2, 1.0f);
    float t = tanh_fast(inner);
    float hx = 0.5f * x;
    return fmaf(hx, t, hx);
}
__device__ __forceinline__ unsigned pack_b2(__nv_bfloat16 a, __nv_bfloat16 b) {
    __nv_bfloat162 t = __halves2bfloat162(a, b);
    return *reinterpret_cast<unsigned*>(&t);
}
__device__ __forceinline__ void split2(float a, float b, unsigned& hi, unsigned& lo) {
    __nv_bfloat16 ha = __float2bfloat16(a), hb = __float2bfloat16(b);
    __nv_bfloat16 la = __float2bfloat16(a - __bfloat162float(ha));
    __nv_bfloat16 lb = __float2bfloat16(b - __bfloat162float(hb));
    hi = pack_b2(ha, hb); lo = pack_b2(la, lb);
}
// consumer-side flag wait: lane 0 polls with backoff, then warp-wide acquire
__device__ __forceinline__ void wait_flag(int* p, int lane) {
    if (lane == 0) {
        while (atomicAdd(p, 0) == 0) __nanosleep(256);
    }
    __syncwarp();
    __threadfence();
}

#define MMA16816(c, a0, a1, a2, a3, b0, b1) \
    asm volatile("mma.sync.aligned.m16n8k16.row.col.f32.bf16.bf16.f32 " \
        "{%0,%1,%2,%3}, {%4,%5,%6,%7}, {%8,%9}, {%0,%1,%2,%3};" \
        : "+f"((c)[0]), "+f"((c)[1]), "+f"((c)[2]), "+f"((c)[3]) \
        : "r"(a0), "r"(a1), "r"(a2), "r"(a3), "r"(b0), "r"(b1))

// ============================================================================
// prep_w: weight images + zero the progress flags (runs before fused kernel
// every graph replay).
// ============================================================================
__global__ void prep_w(const float* __restrict__ W1, const float* __restrict__ Wc1) {
    int idx = blockIdx.x * 256 + threadIdx.x;      // 16 x 256 = 4096
    if (idx < 2048) g_flag[idx] = 0;
    for (int i = idx; i < 32768; i += 4096) {
        int mat = i >> 14;
        int k = (i >> 7) & 127;
        int n = i & 127;
        float v = mat ? Wc1[(5 + k) * 128 + n] : W1[k * 128 + n];
        __nv_bfloat16 hv = __float2bfloat16(v);
        int o = n * 136 + k;
        if (mat) {
            g_B2h[o] = hv;
        } else {
            g_B1h[o] = hv;
            g_B1l[o] = __float2bfloat16(v - __bfloat162float(hv));
        }
    }
}

// ============================================================================
// Fused kernel. Blocks 0-31: p2 consumer role (8 warps = 8 batches each,
// 256 scan warps total, resident from wave 1, flag-gated per 128-step chunk).
// Blocks 32..2079: p1 producer role, s-chunk-major tile order (first 256
// producer CTAs emit chunk 0 of every batch).
// ============================================================================
#define OFF_AH   0
#define OFF_AL   34816
#define OFF_B1H  69632
#define OFF_B1L  104448
#define OFF_B2H  139264
#define OFF_PAR  174080
#define OFF_SB1  (OFF_PAR + 0)
#define OFF_LNG  (OFF_PAR + 512)
#define OFF_LNB  (OFF_PAR + 1024)
#define OFF_BC1  (OFF_PAR + 1536)
#define OFF_WINN (OFF_PAR + 2048)   // 2560 B
#define SMEM_P1  (OFF_PAR + 4608)   // 178688 B

__global__ void __launch_bounds__(256, 1)
fused_kernel(const float* __restrict__ x,    const float* __restrict__ b1,
             const float* __restrict__ ln_g, const float* __restrict__ ln_b,
             const float* __restrict__ Winn, const float* __restrict__ binn,
             const float* __restrict__ bc1,  const float* __restrict__ Wc1,
             const float* __restrict__ Wc2,  const float* __restrict__ bc2,
             const float* __restrict__ corr_scale,
             const float* __restrict__ raw_aL, const float* __restrict__ raw_aT,
             const float* __restrict__ raw_g,  const float* __restrict__ raw_aR,
             const float* __restrict__ omega,  float* __restrict__ out)
{
    extern __shared__ char sm[];

    if (blockIdx.x < 32) {
        // ==================== p2 consumer role ====================
        const int warp = threadIdx.x >> 5, lane = threadIdx.x & 31;
        const int b = (blockIdx.x << 3) + warp;

        const float aL = sigmoidf_(raw_aL[0]) * 0.15f + 0.85f;
        const float aT = sigmoidf_(raw_aT[0]) * 0.25f + 0.70f;
        const float gg = sigmoidf_(raw_g[0])  * 0.20f + 0.80f;
        const float aR = sigmoidf_(raw_aR[0]) * 0.40f;
        const float om = omega[0];
        const float gc = gg * cosf(om), gs = gg * sinf(om), ngs = -gs;
        const float cs = corr_scale[0];

        const int c0 = lane * 4;
        float Ws[5][4], Wo[4][5], bb[5];
#pragma unroll
        for (int i = 0; i < 5; i++)
#pragma unroll
            for (int c = 0; c < 4; c++) Ws[i][c] = Wc1[i*128 + c0 + c];
#pragma unroll
        for (int c = 0; c < 4; c++)
#pragma unroll
            for (int k = 0; k < 5; k++) Wo[c][k] = Wc2[(c0 + c)*5 + k];
#pragma unroll
        for (int k = 0; k < 5; k++) bb[k] = bc2[k];

        float s0 = 0.f, s1 = 0.f, s2 = 0.f, s3 = 0.f, s4 = 0.f;
        const float4* up  = (const float4*)(g_u + (size_t)b * NS * 128);
        const float*  bxp = g_bx + (size_t)b * NS * 8;

        float4 ub[4], xb[4]; float x4b[4];
        const int fb = b << 3;

        for (int ck = 0; ck < 8; ck++) {
            wait_flag(&g_flag[fb + ck], lane);
            wait_flag(&g_flag[fb + (ck < 7 ? ck + 1 : 7)], lane);
            if (ck == 0) {
#pragma unroll
                for (int j = 0; j < 4; j++) {
                    ub[j]  = up[j * 32 + lane];
                    xb[j]  = *(const float4*)(bxp + j * 8);
                    x4b[j] = bxp[j * 8 + 4];
                }
            }
            const int tend = (ck + 1) * 128;
            for (int t0 = ck * 128; t0 < tend; t0 += 4) {
#pragma unroll
                for (int j = 0; j < 4; j++) {
                    const int t = t0 + j;
                    const float4 u = ub[j];
                    const float4 xv = xb[j];
                    const float  x4 = x4b[j];
                    ub[j]  = up[(t + 4) * 32 + lane];
                    xb[j]  = *(const float4*)(bxp + (t + 4) * 8);
                    x4b[j] = bxp[(t + 4) * 8 + 4];

                    float l0 = fmaf(s0, aL, xv.x);
                    float l1 = fmaf(s1, aT, xv.y);
                    float l2 = fmaf(s2, gc, fmaf(s3, gs,  xv.z));
                    float l3 = fmaf(s3, gc, fmaf(s2, ngs, xv.w));
                    float l4 = fmaf(s4, aR, x4);

                    float a0 = u.x, a1 = u.y, a2 = u.z, a3 = u.w;
                    a0 = fmaf(l0, Ws[0][0], a0); a1 = fmaf(l0, Ws[0][1], a1);
                    a2 = fmaf(l0, Ws[0][2], a2); a3 = fmaf(l0, Ws[0][3], a3);
                    a0 = fmaf(l1, Ws[1][0], a0); a1 = fmaf(l1, Ws[1][1], a1);
                    a2 = fmaf(l1, Ws[1][2], a2); a3 = fmaf(l1, Ws[1][3], a3);
                    a0 = fmaf(l2, Ws[2][0], a0); a1 = fmaf(l2, Ws[2][1], a1);
                    a2 = fmaf(l2, Ws[2][2], a2); a3 = fmaf(l2, Ws[2][3], a3);
                    a0 = fmaf(l3, Ws[3][0], a0); a1 = fmaf(l3, Ws[3][1], a1);
                    a2 = fmaf(l3, Ws[3][2], a2); a3 = fmaf(l3, Ws[3][3], a3);
                    a0 = fmaf(l4, Ws[4][0], a0); a1 = fmaf(l4, Ws[4][1], a1);
                    a2 = fmaf(l4, Ws[4][2], a2); a3 = fmaf(l4, Ws[4][3], a3);

                    float m0 = gelu_fast(a0);
                    float m1 = gelu_fast(a1);
                    float m2 = gelu_fast(a2);
                    float m3 = gelu_fast(a3);

                    float p0 = m0*Wo[0][0], p1 = m0*Wo[0][1], p2 = m0*Wo[0][2],
                          p3 = m0*Wo[0][3], p4 = m0*Wo[0][4];
                    p0 = fmaf(m1, Wo[1][0], p0); p1 = fmaf(m1, Wo[1][1], p1);
                    p2 = fmaf(m1, Wo[1][2], p2); p3 = fmaf(m1, Wo[1][3], p3);
                    p4 = fmaf(m1, Wo[1][4], p4);
                    p0 = fmaf(m2, Wo[2][0], p0); p1 = fmaf(m2, Wo[2][1], p1);
                    p2 = fmaf(m2, Wo[2][2], p2); p3 = fmaf(m2, Wo[2][3], p3);
                    p4 = fmaf(m2, Wo[2][4], p4);
                    p0 = fmaf(m3, Wo[3][0], p0); p1 = fmaf(m3, Wo[3][1], p1);
                    p2 = fmaf(m3, Wo[3][2], p2); p3 = fmaf(m3, Wo[3][3], p3);
                    p4 = fmaf(m3, Wo[3][4], p4);

#pragma unroll
                    for (int off = 16; off; off >>= 1) {
                        p0 += __shfl_xor_sync(0xffffffffu, p0, off);
                        p1 += __shfl_xor_sync(0xffffffffu, p1, off);
                        p2 += __shfl_xor_sync(0xffffffffu, p2, off);
                        p3 += __shfl_xor_sync(0xffffffffu, p3, off);
                        p4 += __shfl_xor_sync(0xffffffffu, p4, off);
                    }
                    s0 = fmaf(cs, tanh_fast(p0 + bb[0]), l0);
                    s1 = fmaf(cs, tanh_fast(p1 + bb[1]), l1);
                    s2 = fmaf(cs, tanh_fast(p2 + bb[2]), l2);
                    s3 = fmaf(cs, tanh_fast(p3 + bb[3]), l3);
                    s4 = fmaf(cs, tanh_fast(p4 + bb[4]), l4);
                }
            }
        }

        if (lane == 0) {
            out[b*5+0] = s0; out[b*5+1] = s1; out[b*5+2] = s2;
            out[b*5+3] = s3; out[b*5+4] = s4;
        }
        return;
    }

    // ==================== p1 producer role ====================
    const int pidx = blockIdx.x - 32;
    const int pb = pidx & 255;          // batch
    const int pk = pidx >> 8;           // s-chunk (0..7) — chunk-major order
    const int row0 = (pb << 10) + (pk << 7);

    const int tid = threadIdx.x;
    const int wid = tid >> 5, lane = tid & 31;
    const int g = lane >> 2, q = lane & 3;

    uint16_t* pAh = (uint16_t*)(sm + OFF_AH);
    uint16_t* pAl = (uint16_t*)(sm + OFF_AL);
    const uint16_t* pB1h = (const uint16_t*)(sm + OFF_B1H);
    const uint16_t* pB1l = (const uint16_t*)(sm + OFF_B1L);
    const uint16_t* pB2h = (const uint16_t*)(sm + OFF_B2H);

    if (tid < 128) {
        ((float*)(sm + OFF_SB1))[tid] = b1[tid];
        ((float*)(sm + OFF_LNG))[tid] = ln_g[tid];
        ((float*)(sm + OFF_LNB))[tid] = ln_b[tid];
        ((float*)(sm + OFF_BC1))[tid] = bc1[tid];
    }
    for (int i = tid; i < 640; i += 256) ((float*)(sm + OFF_WINN))[i] = Winn[i];
    {
        const uint4* s1h = (const uint4*)g_B1h; const uint4* s1l = (const uint4*)g_B1l;
        const uint4* s2h = (const uint4*)g_B2h;
        uint4* d1h = (uint4*)pAh;  // placate compiler; real targets below
        (void)d1h;
        uint4* t1h = (uint4*)pB1h; uint4* t1l = (uint4*)pB1l;
        uint4* t2h = (uint4*)pB2h;
        for (int i = tid; i < 2176; i += 256) {
            t1h[i] = s1h[i]; t1l[i] = s1l[i]; t2h[i] = s2h[i];
        }
    }
    {
        const float4* xt = (const float4*)(x + (size_t)row0 * 128);
        for (int i = tid; i < 4096; i += 256) {
            float4 v = xt[i];
            int row = i >> 5, k4 = (i & 31) * 4;
            unsigned h0, l0, h1, l1;
            split2(v.x, v.y, h0, l0);
            split2(v.z, v.w, h1, l1);
            *(uint2*)&pAh[row * 136 + k4] = make_uint2(h0, h1);
            *(uint2*)&pAl[row * 136 + k4] = make_uint2(l0, l1);
        }
    }
    __syncthreads();

    const int rA = wid * 16 + g;
    const int rB = rA + 8;

    // ---- GEMM1: acc = x @ W1 (3-term bf16 split) ----
    float acc[16][4];
#pragma unroll
    for (int nc = 0; nc < 16; nc++)
#pragma unroll
        for (int j = 0; j < 4; j++) acc[nc][j] = 0.f;

#pragma unroll 2
    for (int kc = 0; kc < 8; kc++) {
        const int k0 = kc * 16;
        unsigned ah0 = *(const unsigned*)&pAh[rA * 136 + k0 + 2 * q];
        unsigned ah1 = *(const unsigned*)&pAh[rB * 136 + k0 + 2 * q];
        unsigned ah2 = *(const unsigned*)&pAh[rA * 136 + k0 + 8 + 2 * q];
        unsigned ah3 = *(const unsigned*)&pAh[rB * 136 + k0 + 8 + 2 * q];
        unsigned al0 = *(const unsigned*)&pAl[rA * 136 + k0 + 2 * q];
        unsigned al1 = *(const unsigned*)&pAl[rB * 136 + k0 + 2 * q];
        unsigned al2 = *(const unsigned*)&pAl[rA * 136 + k0 + 8 + 2 * q];
        unsigned al3 = *(const unsigned*)&pAl[rB * 136 + k0 + 8 + 2 * q];
#pragma unroll
        for (int nc = 0; nc < 16; nc++) {
            const int nb = (nc * 8 + g) * 136 + k0 + 2 * q;
            unsigned bh0 = *(const unsigned*)&pB1h[nb];
            unsigned bh1 = *(const unsigned*)&pB1h[nb + 8];
            unsigned bl0 = *(const unsigned*)&pB1l[nb];
            unsigned bl1 = *(const unsigned*)&pB1l[nb + 8];
            MMA16816(acc[nc], ah0, ah1, ah2, ah3, bh0, bh1);
            MMA16816(acc[nc], ah0, ah1, ah2, ah3, bl0, bl1);
            MMA16816(acc[nc], al0, al1, al2, al3, bh0, bh1);
        }
    }

    // ---- Epilogue A ----
    const float* sB1 = (const float*)(sm + OFF_SB1);
    const float* sLG = (const float*)(sm + OFF_LNG);
    const float* sLB = (const float*)(sm + OFF_LNB);
    const float* sWn = (const float*)(sm + OFF_WINN);

    float sumA = 0.f, sqA = 0.f, sumB = 0.f, sqB = 0.f;
#pragma unroll
    for (int nc = 0; nc < 16; nc++) {
        const int cc0 = nc * 8 + 2 * q;
        float v0 = acc[nc][0] + sB1[cc0], v1 = acc[nc][1] + sB1[cc0 + 1];
        float v2 = acc[nc][2] + sB1[cc0], v3 = acc[nc][3] + sB1[cc0 + 1];
        acc[nc][0] = v0; acc[nc][1] = v1; acc[nc][2] = v2; acc[nc][3] = v3;
        sumA += v0 + v1; sqA = fmaf(v0, v0, fmaf(v1, v1, sqA));
        sumB += v2 + v3; sqB = fmaf(v2, v2, fmaf(v3, v3, sqB));
    }
#pragma unroll
    for (int off = 1; off <= 2; off <<= 1) {
        sumA += __shfl_xor_sync(0xffffffffu, sumA, off);
        sqA  += __shfl_xor_sync(0xffffffffu, sqA,  off);
        sumB += __shfl_xor_sync(0xffffffffu, sumB, off);
        sqB  += __shfl_xor_sync(0xffffffffu, sqB,  off);
    }
    const float muA = sumA * 0.0078125f;
    const float rsA = rsqrtf(sqA * 0.0078125f - muA * muA + 1e-5f);
    const float muB = sumB * 0.0078125f;
    const float rsB = rsqrtf(sqB * 0.0078125f - muB * muB + 1e-5f);

    float bxA[5] = {0, 0, 0, 0, 0}, bxB[5] = {0, 0, 0, 0, 0};
#pragma unroll
    for (int nc = 0; nc < 16; nc++) {
        const int cc0 = nc * 8 + 2 * q;
        float h0 = gelu_exact((acc[nc][0] - muA) * rsA * sLG[cc0]     + sLB[cc0]);
        float h1 = gelu_exact((acc[nc][1] - muA) * rsA * sLG[cc0 + 1] + sLB[cc0 + 1]);
        float h2 = gelu_exact((acc[nc][2] - muB) * rsB * sLG[cc0]     + sLB[cc0]);
        float h3 = gelu_exact((acc[nc][3] - muB) * rsB * sLG[cc0 + 1] + sLB[cc0 + 1]);
        acc[nc][0] = h0; acc[nc][1] = h1; acc[nc][2] = h2; acc[nc][3] = h3;
#pragma unroll
        for (int j = 0; j < 5; j++) {
            bxA[j] = fmaf(h0, sWn[cc0 * 5 + j], fmaf(h1, sWn[(cc0 + 1) * 5 + j], bxA[j]));
            bxB[j] = fmaf(h2, sWn[cc0 * 5 + j], fmaf(h3, sWn[(cc0 + 1) * 5 + j], bxB[j]));
        }
    }
#pragma unroll
    for (int off = 1; off <= 2; off <<= 1)
#pragma unroll
        for (int j = 0; j < 5; j++) {
            bxA[j] += __shfl_xor_sync(0xffffffffu, bxA[j], off);
            bxB[j] += __shfl_xor_sync(0xffffffffu, bxB[j], off);
        }
    if (q == 0) {
#pragma unroll
        for (int j = 0; j < 5; j++) {
            float bn = __ldg(&binn[j]);
            g_bx[(size_t)(row0 + rA) * 8 + j] = bxA[j] + bn;
            g_bx[(size_t)(row0 + rB) * 8 + j] = bxB[j] + bn;
        }
    }

    // repack h into GEMM2 A-fragments (hi only — corr_scale-damped path)
    unsigned fh[8][4];
#pragma unroll
    for (int kc = 0; kc < 8; kc++) {
        fh[kc][0] = pack_b2(__float2bfloat16(acc[2*kc][0]),     __float2bfloat16(acc[2*kc][1]));
        fh[kc][1] = pack_b2(__float2bfloat16(acc[2*kc][2]),     __float2bfloat16(acc[2*kc][3]));
        fh[kc][2] = pack_b2(__float2bfloat16(acc[2*kc + 1][0]), __float2bfloat16(acc[2*kc + 1][1]));
        fh[kc][3] = pack_b2(__float2bfloat16(acc[2*kc + 1][2]), __float2bfloat16(acc[2*kc + 1][3]));
    }

    // ---- GEMM2: acc = h @ Wc1[5:,:]  (single-term bf16) ----
#pragma unroll
    for (int nc = 0; nc < 16; nc++)
#pragma unroll
        for (int j = 0; j < 4; j++) acc[nc][j] = 0.f;

#pragma unroll 2
    for (int kc = 0; kc < 8; kc++) {
        const int k0 = kc * 16;
#pragma unroll
        for (int nc = 0; nc < 16; nc++) {
            const int nb = (nc * 8 + g) * 136 + k0 + 2 * q;
            unsigned bh0 = *(const unsigned*)&pB2h[nb];
            unsigned bh1 = *(const unsigned*)&pB2h[nb + 8];
            MMA16816(acc[nc], fh[kc][0], fh[kc][1], fh[kc][2], fh[kc][3], bh0, bh1);
        }
    }

    // ---- Epilogue B: +bc1 -> g_u ----
    const float* sBC = (const float*)(sm + OFF_BC1);
    const size_t gra = (size_t)(row0 + rA) * 128;
    const size_t grb = (size_t)(row0 + rB) * 128;
#pragma unroll
    for (int nc = 0; nc < 16; nc++) {
        const int cc0 = nc * 8 + 2 * q;
        float bA = sBC[cc0], bB = sBC[cc0 + 1];
        *(float2*)&g_u[gra + cc0] = make_float2(acc[nc][0] + bA, acc[nc][1] + bB);
        *(float2*)&g_u[grb + cc0] = make_float2(acc[nc][2] + bA, acc[nc][3] + bB);
    }

    // ---- publish tile (b, k) ----
    __syncthreads();
    if (tid == 0) {
        __threadfence();
        atomicExch(&g_flag[(pb << 3) + pk], 1);
    }
}

// ============================================================================
extern "C" void kernel_launch(void* const* d_in, const int* in_sizes, int n_in,
                              void* d_out, int out_size)
{
    (void)in_sizes; (void)n_in; (void)out_size;
    const float* x    = (const float*)d_in[0];
    const float* W1   = (const float*)d_in[1];
    const float* b1   = (const float*)d_in[2];
    const float* ln_g = (const float*)d_in[3];
    const float* ln_b = (const float*)d_in[4];
    const float* Winn = (const float*)d_in[5];
    const float* binn = (const float*)d_in[6];
    const float* Wc1  = (const float*)d_in[7];
    const float* bc1  = (const float*)d_in[8];
    const float* Wc2  = (const float*)d_in[9];
    const float* bc2  = (const float*)d_in[10];
    const float* cscl = (const float*)d_in[11];
    const float* raL  = (const float*)d_in[12];
    const float* raT  = (const float*)d_in[13];
    const float* rg   = (const float*)d_in[14];
    const float* raR  = (const float*)d_in[15];
    const float* om   = (const float*)d_in[16];

    static int smem_set = 0;
    if (!smem_set) {
        cudaFuncSetAttribute(fused_kernel, cudaFuncAttributeMaxDynamicSharedMemorySize, SMEM_P1);
        smem_set = 1;
    }

    prep_w<<<16, 256>>>(W1, Wc1);
    fused_kernel<<<2080, 256, SMEM_P1>>>(x, b1, ln_g, ln_b, Winn, binn, bc1,
                                         Wc1, Wc2, bc2, cscl, raL, raT, rg, raR, om,
                                         (float*)d_out);
}

// round 12
// speedup vs baseline: 6.4264x; 6.4264x over previous
#include <cuda_runtime.h>
#include <cuda_bf16.h>
#include <math.h>
#include <stdint.h>

// Problem constants
#define NB   256
#define NS   1024
#define NROWS (NB * NS)   // 262144

// Scratch (device globals; padded by 4 rows for branch-free depth-4 prefetch)
__device__ float g_u[(size_t)NROWS * 128 + 512];
__device__ float g_bx[(size_t)NROWS * 8 + 32];
// bf16 weight images, transposed to [n][k], row stride 136 elements
// B1 needs hi+lo (bx path undamped); B2 needs hi only (corr_scale-damped)
__device__ __nv_bfloat16 g_B1h[17408], g_B1l[17408], g_B2h[17408];

// ---------------- math helpers ----------------
__device__ __forceinline__ float gelu_exact(float x) {
    return 0.5f * x * (1.0f + erff(x * 0.7071067811865475f));
}
__device__ __forceinline__ float sigmoidf_(float v) { return 1.0f / (1.0f + expf(-v)); }
__device__ __forceinline__ float tanh_fast(float x) {
    float y; asm("tanh.approx.f32 %0, %1;" : "=f"(y) : "f"(x)); return y;
}
__device__ __forceinline__ float gelu_fast(float x) {
    float x2 = x * x;
    float inner = 0.7978845608f * x * fmaf(0.044715f, x2, 1.0f);
    float t = tanh_fast(inner);
    float hx = 0.5f * x;
    return fmaf(hx, t, hx);
}
__device__ __forceinline__ unsigned pack_b2(__nv_bfloat16 a, __nv_bfloat16 b) {
    __nv_bfloat162 t = __halves2bfloat162(a, b);
    return *reinterpret_cast<unsigned*>(&t);
}
__device__ __forceinline__ void split2(float a, float b, unsigned& hi, unsigned& lo) {
    __nv_bfloat16 ha = __float2bfloat16(a), hb = __float2bfloat16(b);
    __nv_bfloat16 la = __float2bfloat16(a - __bfloat162float(ha));
    __nv_bfloat16 lb = __float2bfloat16(b - __bfloat162float(hb));
    hi = pack_b2(ha, hb); lo = pack_b2(la, lb);
}

#define MMA16816(c, a0, a1, a2, a3, b0, b1) \
    asm volatile("mma.sync.aligned.m16n8k16.row.col.f32.bf16.bf16.f32 " \
        "{%0,%1,%2,%3}, {%4,%5,%6,%7}, {%8,%9}, {%0,%1,%2,%3};" \
        : "+f"((c)[0]), "+f"((c)[1]), "+f"((c)[2]), "+f"((c)[3]) \
        : "r"(a0), "r"(a1), "r"(a2), "r"(a3), "r"(b0), "r"(b1))

// ============================================================================
// prep_w: W1 (k,n) -> bf16 hi/lo images; Wc1[5:,:] -> bf16 hi image.
// Layout [n][k], row stride 136.
// ============================================================================
__global__ void prep_w(const float* __restrict__ W1, const float* __restrict__ Wc1) {
    int idx = blockIdx.x * 256 + threadIdx.x;
    for (int i = idx; i < 32768; i += 4096) {
        int mat = i >> 14;
        int k = (i >> 7) & 127;
        int n = i & 127;
        float v = mat ? Wc1[(5 + k) * 128 + n] : W1[k * 128 + n];
        __nv_bfloat16 hv = __float2bfloat16(v);
        int o = n * 136 + k;
        if (mat) {
            g_B2h[o] = hv;
        } else {
            g_B1h[o] = hv;
            g_B1l[o] = __float2bfloat16(v - __bfloat162float(hv));
        }
    }
}

// ============================================================================
// p1_mma (unchanged from R9 best): 3-term GEMM1, single-term GEMM2.
// ============================================================================
#define OFF_AH   0
#define OFF_AL   34816
#define OFF_B1H  69632
#define OFF_B1L  104448
#define OFF_B2H  139264
#define OFF_PAR  174080
#define OFF_SB1  (OFF_PAR + 0)
#define OFF_LNG  (OFF_PAR + 512)
#define OFF_LNB  (OFF_PAR + 1024)
#define OFF_BC1  (OFF_PAR + 1536)
#define OFF_WINN (OFF_PAR + 2048)   // 2560 B
#define SMEM_P1  (OFF_PAR + 4608)   // 178688 B

__global__ void __launch_bounds__(256, 1)
p1_mma(const float* __restrict__ x,    const float* __restrict__ b1,
       const float* __restrict__ ln_g, const float* __restrict__ ln_b,
       const float* __restrict__ Winn, const float* __restrict__ binn,
       const float* __restrict__ bc1)
{
    extern __shared__ char sm[];
    const int tid = threadIdx.x;
    const int wid = tid >> 5, lane = tid & 31;
    const int g = lane >> 2, q = lane & 3;
    const int row0 = blockIdx.x * 128;

    uint16_t* pAh = (uint16_t*)(sm + OFF_AH);
    uint16_t* pAl = (uint16_t*)(sm + OFF_AL);
    const uint16_t* pB1h = (const uint16_t*)(sm + OFF_B1H);
    const uint16_t* pB1l = (const uint16_t*)(sm + OFF_B1L);
    const uint16_t* pB2h = (const uint16_t*)(sm + OFF_B2H);

    if (tid < 128) {
        ((float*)(sm + OFF_SB1))[tid] = b1[tid];
        ((float*)(sm + OFF_LNG))[tid] = ln_g[tid];
        ((float*)(sm + OFF_LNB))[tid] = ln_b[tid];
        ((float*)(sm + OFF_BC1))[tid] = bc1[tid];
    }
    for (int i = tid; i < 640; i += 256) ((float*)(sm + OFF_WINN))[i] = Winn[i];
    {
        const uint4* s1h = (const uint4*)g_B1h; const uint4* s1l = (const uint4*)g_B1l;
        const uint4* s2h = (const uint4*)g_B2h;
        uint4* d1h = (uint4*)pB1h; uint4* d1l = (uint4*)pB1l;
        uint4* d2h = (uint4*)pB2h;
        for (int i = tid; i < 2176; i += 256) {
            d1h[i] = s1h[i]; d1l[i] = s1l[i]; d2h[i] = s2h[i];
        }
    }
    {
        const float4* xt = (const float4*)(x + (size_t)row0 * 128);
        for (int i = tid; i < 4096; i += 256) {
            float4 v = xt[i];
            int row = i >> 5, k4 = (i & 31) * 4;
            unsigned h0, l0, h1, l1;
            split2(v.x, v.y, h0, l0);
            split2(v.z, v.w, h1, l1);
            *(uint2*)&pAh[row * 136 + k4] = make_uint2(h0, h1);
            *(uint2*)&pAl[row * 136 + k4] = make_uint2(l0, l1);
        }
    }
    __syncthreads();

    const int rA = wid * 16 + g;
    const int rB = rA + 8;

    // ---- GEMM1: acc = x @ W1 (3-term bf16 split) ----
    float acc[16][4];
#pragma unroll
    for (int nc = 0; nc < 16; nc++)
#pragma unroll
        for (int j = 0; j < 4; j++) acc[nc][j] = 0.f;

#pragma unroll 2
    for (int kc = 0; kc < 8; kc++) {
        const int k0 = kc * 16;
        unsigned ah0 = *(const unsigned*)&pAh[rA * 136 + k0 + 2 * q];
        unsigned ah1 = *(const unsigned*)&pAh[rB * 136 + k0 + 2 * q];
        unsigned ah2 = *(const unsigned*)&pAh[rA * 136 + k0 + 8 + 2 * q];
        unsigned ah3 = *(const unsigned*)&pAh[rB * 136 + k0 + 8 + 2 * q];
        unsigned al0 = *(const unsigned*)&pAl[rA * 136 + k0 + 2 * q];
        unsigned al1 = *(const unsigned*)&pAl[rB * 136 + k0 + 2 * q];
        unsigned al2 = *(const unsigned*)&pAl[rA * 136 + k0 + 8 + 2 * q];
        unsigned al3 = *(const unsigned*)&pAl[rB * 136 + k0 + 8 + 2 * q];
#pragma unroll
        for (int nc = 0; nc < 16; nc++) {
            const int nb = (nc * 8 + g) * 136 + k0 + 2 * q;
            unsigned bh0 = *(const unsigned*)&pB1h[nb];
            unsigned bh1 = *(const unsigned*)&pB1h[nb + 8];
            unsigned bl0 = *(const unsigned*)&pB1l[nb];
            unsigned bl1 = *(const unsigned*)&pB1l[nb + 8];
            MMA16816(acc[nc], ah0, ah1, ah2, ah3, bh0, bh1);
            MMA16816(acc[nc], ah0, ah1, ah2, ah3, bl0, bl1);
            MMA16816(acc[nc], al0, al1, al2, al3, bh0, bh1);
        }
    }

    // ---- Epilogue A ----
    const float* sB1 = (const float*)(sm + OFF_SB1);
    const float* sLG = (const float*)(sm + OFF_LNG);
    const float* sLB = (const float*)(sm + OFF_LNB);
    const float* sWn = (const float*)(sm + OFF_WINN);

    float sumA = 0.f, sqA = 0.f, sumB = 0.f, sqB = 0.f;
#pragma unroll
    for (int nc = 0; nc < 16; nc++) {
        const int c0 = nc * 8 + 2 * q;
        float v0 = acc[nc][0] + sB1[c0], v1 = acc[nc][1] + sB1[c0 + 1];
        float v2 = acc[nc][2] + sB1[c0], v3 = acc[nc][3] + sB1[c0 + 1];
        acc[nc][0] = v0; acc[nc][1] = v1; acc[nc][2] = v2; acc[nc][3] = v3;
        sumA += v0 + v1; sqA = fmaf(v0, v0, fmaf(v1, v1, sqA));
        sumB += v2 + v3; sqB = fmaf(v2, v2, fmaf(v3, v3, sqB));
    }
#pragma unroll
    for (int off = 1; off <= 2; off <<= 1) {
        sumA += __shfl_xor_sync(0xffffffffu, sumA, off);
        sqA  += __shfl_xor_sync(0xffffffffu, sqA,  off);
        sumB += __shfl_xor_sync(0xffffffffu, sumB, off);
        sqB  += __shfl_xor_sync(0xffffffffu, sqB,  off);
    }
    const float muA = sumA * 0.0078125f;
    const float rsA = rsqrtf(sqA * 0.0078125f - muA * muA + 1e-5f);
    const float muB = sumB * 0.0078125f;
    const float rsB = rsqrtf(sqB * 0.0078125f - muB * muB + 1e-5f);

    float bxA[5] = {0, 0, 0, 0, 0}, bxB[5] = {0, 0, 0, 0, 0};
#pragma unroll
    for (int nc = 0; nc < 16; nc++) {
        const int c0 = nc * 8 + 2 * q;
        float h0 = gelu_exact((acc[nc][0] - muA) * rsA * sLG[c0]     + sLB[c0]);
        float h1 = gelu_exact((acc[nc][1] - muA) * rsA * sLG[c0 + 1] + sLB[c0 + 1]);
        float h2 = gelu_exact((acc[nc][2] - muB) * rsB * sLG[c0]     + sLB[c0]);
        float h3 = gelu_exact((acc[nc][3] - muB) * rsB * sLG[c0 + 1] + sLB[c0 + 1]);
        acc[nc][0] = h0; acc[nc][1] = h1; acc[nc][2] = h2; acc[nc][3] = h3;
#pragma unroll
        for (int j = 0; j < 5; j++) {
            bxA[j] = fmaf(h0, sWn[c0 * 5 + j], fmaf(h1, sWn[(c0 + 1) * 5 + j], bxA[j]));
            bxB[j] = fmaf(h2, sWn[c0 * 5 + j], fmaf(h3, sWn[(c0 + 1) * 5 + j], bxB[j]));
        }
    }
#pragma unroll
    for (int off = 1; off <= 2; off <<= 1)
#pragma unroll
        for (int j = 0; j < 5; j++) {
            bxA[j] += __shfl_xor_sync(0xffffffffu, bxA[j], off);
            bxB[j] += __shfl_xor_sync(0xffffffffu, bxB[j], off);
        }
    if (q == 0) {
#pragma unroll
        for (int j = 0; j < 5; j++) {
            float bn = __ldg(&binn[j]);
            g_bx[(size_t)(row0 + rA) * 8 + j] = bxA[j] + bn;
            g_bx[(size_t)(row0 + rB) * 8 + j] = bxB[j] + bn;
        }
    }

    // repack h into GEMM2 A-fragments (hi only — GEMM2 is corr_scale-damped)
    unsigned fh[8][4];
#pragma unroll
    for (int kc = 0; kc < 8; kc++) {
        fh[kc][0] = pack_b2(__float2bfloat16(acc[2*kc][0]),     __float2bfloat16(acc[2*kc][1]));
        fh[kc][1] = pack_b2(__float2bfloat16(acc[2*kc][2]),     __float2bfloat16(acc[2*kc][3]));
        fh[kc][2] = pack_b2(__float2bfloat16(acc[2*kc + 1][0]), __float2bfloat16(acc[2*kc + 1][1]));
        fh[kc][3] = pack_b2(__float2bfloat16(acc[2*kc + 1][2]), __float2bfloat16(acc[2*kc + 1][3]));
    }

    // ---- GEMM2: acc = h @ Wc1[5:,:]  (single-term bf16) ----
#pragma unroll
    for (int nc = 0; nc < 16; nc++)
#pragma unroll
        for (int j = 0; j < 4; j++) acc[nc][j] = 0.f;

#pragma unroll 2
    for (int kc = 0; kc < 8; kc++) {
        const int k0 = kc * 16;
#pragma unroll
        for (int nc = 0; nc < 16; nc++) {
            const int nb = (nc * 8 + g) * 136 + k0 + 2 * q;
            unsigned bh0 = *(const unsigned*)&pB2h[nb];
            unsigned bh1 = *(const unsigned*)&pB2h[nb + 8];
            MMA16816(acc[nc], fh[kc][0], fh[kc][1], fh[kc][2], fh[kc][3], bh0, bh1);
        }
    }

    // ---- Epilogue B: +bc1 -> g_u ----
    const float* sBC = (const float*)(sm + OFF_BC1);
    const size_t gra = (size_t)(row0 + rA) * 128;
    const size_t grb = (size_t)(row0 + rB) * 128;
#pragma unroll
    for (int nc = 0; nc < 16; nc++) {
        const int c0 = nc * 8 + 2 * q;
        float bA = sBC[c0], bB = sBC[c0 + 1];
        *(float2*)&g_u[gra + c0] = make_float2(acc[nc][0] + bA, acc[nc][1] + bB);
        *(float2*)&g_u[grb + c0] = make_float2(acc[nc][2] + bA, acc[nc][3] + bB);
    }
}

// ============================================================================
// Phase 2: one warp per batch, 256 blocks, depth-4 register prefetch, MUFU
// transcendentals. NEW (R12): asymmetric split butterfly — exact fp32,
// 20 SHFL/step instead of 25:
//   stage A: 1 level (off 16) on all 5 values           -> 5 shfl
//   stage B: halves specialize {p0,p1,p2} / {p3,p4}, 4 levels x 3 -> 12 shfl
//   stage C: cross-half exchange (off 16)               -> 3 shfl
// ============================================================================
__global__ void __launch_bounds__(32)
p2_kernel(const float* __restrict__ Wc1, const float* __restrict__ Wc2,
          const float* __restrict__ bc2, const float* __restrict__ corr_scale,
          const float* __restrict__ raw_aL, const float* __restrict__ raw_aT,
          const float* __restrict__ raw_g,  const float* __restrict__ raw_aR,
          const float* __restrict__ omega,  float* __restrict__ out)
{
    const int lane = threadIdx.x & 31;
    const bool hi_half = (lane & 16) != 0;
    const int b = blockIdx.x;

    const float aL = sigmoidf_(raw_aL[0]) * 0.15f + 0.85f;
    const float aT = sigmoidf_(raw_aT[0]) * 0.25f + 0.70f;
    const float gg = sigmoidf_(raw_g[0])  * 0.20f + 0.80f;
    const float aR = sigmoidf_(raw_aR[0]) * 0.40f;
    const float om = omega[0];
    const float gc = gg * cosf(om), gs = gg * sinf(om), ngs = -gs;
    const float cs = corr_scale[0];

    const int c0 = lane * 4;
    float Ws[5][4], Wo[4][5], bb[5];
#pragma unroll
    for (int i = 0; i < 5; i++)
#pragma unroll
        for (int c = 0; c < 4; c++) Ws[i][c] = Wc1[i*128 + c0 + c];
#pragma unroll
    for (int c = 0; c < 4; c++)
#pragma unroll
        for (int k = 0; k < 5; k++) Wo[c][k] = Wc2[(c0 + c)*5 + k];
#pragma unroll
    for (int k = 0; k < 5; k++) bb[k] = bc2[k];

    float s0 = 0.f, s1 = 0.f, s2 = 0.f, s3 = 0.f, s4 = 0.f;
    const float4* up  = (const float4*)(g_u + (size_t)b * NS * 128);
    const float*  bxp = g_bx + (size_t)b * NS * 8;

    float4 ub[4], xb[4]; float x4b[4];
#pragma unroll
    for (int j = 0; j < 4; j++) {
        ub[j]  = up[j * 32 + lane];
        xb[j]  = *(const float4*)(bxp + j * 8);
        x4b[j] = bxp[j * 8 + 4];
    }

    for (int t0 = 0; t0 < NS; t0 += 4) {
#pragma unroll
        for (int j = 0; j < 4; j++) {
            const int t = t0 + j;
            const float4 u = ub[j];
            const float4 x = xb[j];
            const float  x4 = x4b[j];
            ub[j]  = up[(t + 4) * 32 + lane];
            xb[j]  = *(const float4*)(bxp + (t + 4) * 8);
            x4b[j] = bxp[(t + 4) * 8 + 4];

            float l0 = fmaf(s0, aL, x.x);
            float l1 = fmaf(s1, aT, x.y);
            float l2 = fmaf(s2, gc, fmaf(s3, gs,  x.z));
            float l3 = fmaf(s3, gc, fmaf(s2, ngs, x.w));
            float l4 = fmaf(s4, aR, x4);

            float a0 = u.x, a1 = u.y, a2 = u.z, a3 = u.w;
            a0 = fmaf(l0, Ws[0][0], a0); a1 = fmaf(l0, Ws[0][1], a1);
            a2 = fmaf(l0, Ws[0][2], a2); a3 = fmaf(l0, Ws[0][3], a3);
            a0 = fmaf(l1, Ws[1][0], a0); a1 = fmaf(l1, Ws[1][1], a1);
            a2 = fmaf(l1, Ws[1][2], a2); a3 = fmaf(l1, Ws[1][3], a3);
            a0 = fmaf(l2, Ws[2][0], a0); a1 = fmaf(l2, Ws[2][1], a1);
            a2 = fmaf(l2, Ws[2][2], a2); a3 = fmaf(l2, Ws[2][3], a3);
            a0 = fmaf(l3, Ws[3][0], a0); a1 = fmaf(l3, Ws[3][1], a1);
            a2 = fmaf(l3, Ws[3][2], a2); a3 = fmaf(l3, Ws[3][3], a3);
            a0 = fmaf(l4, Ws[4][0], a0); a1 = fmaf(l4, Ws[4][1], a1);
            a2 = fmaf(l4, Ws[4][2], a2); a3 = fmaf(l4, Ws[4][3], a3);

            float m0 = gelu_fast(a0);
            float m1 = gelu_fast(a1);
            float m2 = gelu_fast(a2);
            float m3 = gelu_fast(a3);

            float p0 = m0*Wo[0][0], p1 = m0*Wo[0][1], p2 = m0*Wo[0][2],
                  p3 = m0*Wo[0][3], p4 = m0*Wo[0][4];
            p0 = fmaf(m1, Wo[1][0], p0); p1 = fmaf(m1, Wo[1][1], p1);
            p2 = fmaf(m1, Wo[1][2], p2); p3 = fmaf(m1, Wo[1][3], p3);
            p4 = fmaf(m1, Wo[1][4], p4);
            p0 = fmaf(m2, Wo[2][0], p0); p1 = fmaf(m2, Wo[2][1], p1);
            p2 = fmaf(m2, Wo[2][2], p2); p3 = fmaf(m2, Wo[2][3], p3);
            p4 = fmaf(m2, Wo[2][4], p4);
            p0 = fmaf(m3, Wo[3][0], p0); p1 = fmaf(m3, Wo[3][1], p1);
            p2 = fmaf(m3, Wo[3][2], p2); p3 = fmaf(m3, Wo[3][3], p3);
            p4 = fmaf(m3, Wo[3][4], p4);

            // ---- stage A: fold halves (off 16), all 5 values ----
            p0 += __shfl_xor_sync(0xffffffffu, p0, 16);
            p1 += __shfl_xor_sync(0xffffffffu, p1, 16);
            p2 += __shfl_xor_sync(0xffffffffu, p2, 16);
            p3 += __shfl_xor_sync(0xffffffffu, p3, 16);
            p4 += __shfl_xor_sync(0xffffffffu, p4, 16);

            // ---- stage B: halves specialize; 4 levels within 16-lane halves ----
            float q0 = hi_half ? p3 : p0;
            float q1 = hi_half ? p4 : p1;
            float q2 = hi_half ? 0.f : p2;
#pragma unroll
            for (int off = 8; off; off >>= 1) {
                q0 += __shfl_xor_sync(0xffffffffu, q0, off);
                q1 += __shfl_xor_sync(0xffffffffu, q1, off);
                q2 += __shfl_xor_sync(0xffffffffu, q2, off);
            }
            // lanes 0-15: q0=P0, q1=P1, q2=P2;  lanes 16-31: q0=P3, q1=P4

            // ---- stage C: cross-half exchange ----
            float e0 = __shfl_xor_sync(0xffffffffu, q0, 16);  // lo:P3  hi:P0
            float e1 = __shfl_xor_sync(0xffffffffu, q1, 16);  // lo:P4  hi:P1
            float e2 = __shfl_xor_sync(0xffffffffu, q2, 16);  // lo:--  hi:P2

            float P0 = hi_half ? e0 : q0;
            float P1 = hi_half ? e1 : q1;
            float P2 = hi_half ? e2 : q2;
            float P3 = hi_half ? q0 : e0;
            float P4 = hi_half ? q1 : e1;

            s0 = fmaf(cs, tanh_fast(P0 + bb[0]), l0);
            s1 = fmaf(cs, tanh_fast(P1 + bb[1]), l1);
            s2 = fmaf(cs, tanh_fast(P2 + bb[2]), l2);
            s3 = fmaf(cs, tanh_fast(P3 + bb[3]), l3);
            s4 = fmaf(cs, tanh_fast(P4 + bb[4]), l4);
        }
    }

    if (lane == 0) {
        out[b*5+0] = s0; out[b*5+1] = s1; out[b*5+2] = s2;
        out[b*5+3] = s3; out[b*5+4] = s4;
    }
}

// ============================================================================
extern "C" void kernel_launch(void* const* d_in, const int* in_sizes, int n_in,
                              void* d_out, int out_size)
{
    (void)in_sizes; (void)n_in; (void)out_size;
    const float* x    = (const float*)d_in[0];
    const float* W1   = (const float*)d_in[1];
    const float* b1   = (const float*)d_in[2];
    const float* ln_g = (const float*)d_in[3];
    const float* ln_b = (const float*)d_in[4];
    const float* Winn = (const float*)d_in[5];
    const float* binn = (const float*)d_in[6];
    const float* Wc1  = (const float*)d_in[7];
    const float* bc1  = (const float*)d_in[8];
    const float* Wc2  = (const float*)d_in[9];
    const float* bc2  = (const float*)d_in[10];
    const float* cscl = (const float*)d_in[11];
    const float* raL  = (const float*)d_in[12];
    const float* raT  = (const float*)d_in[13];
    const float* rg   = (const float*)d_in[14];
    const float* raR  = (const float*)d_in[15];
    const float* om   = (const float*)d_in[16];

    static int smem_set = 0;
    if (!smem_set) {
        cudaFuncSetAttribute(p1_mma, cudaFuncAttributeMaxDynamicSharedMemorySize, SMEM_P1);
        smem_set = 1;
    }

    prep_w<<<16, 256>>>(W1, Wc1);
    p1_mma<<<NROWS / 128, 256, SMEM_P1>>>(x, b1, ln_g, ln_b, Winn, binn, bc1);
    p2_kernel<<<NB, 32>>>(Wc1, Wc2, bc2, cscl, raL, raT, rg, raR, om, (float*)d_out);
}

// round 13
// speedup vs baseline: 7.9551x; 1.2379x over previous
#include <cuda_runtime.h>
#include <cuda_bf16.h>
#include <math.h>
#include <stdint.h>

// Problem constants
#define NB   256
#define NS   1024
#define NROWS (NB * NS)   // 262144

// Scratch (device globals; padded for branch-free depth-4 prefetch)
__device__ float g_u[(size_t)NROWS * 128 + 512];
__device__ float g_bx[(size_t)NROWS * 8 + 32];
__device__ float g_state[NB * 5];
// bf16 weight images, transposed to [n][k], row stride 136 elements
__device__ __nv_bfloat16 g_B1h[17408], g_B1l[17408], g_B2h[17408];

// ---------------- math helpers ----------------
__device__ __forceinline__ float gelu_exact(float x) {
    return 0.5f * x * (1.0f + erff(x * 0.7071067811865475f));
}
__device__ __forceinline__ float sigmoidf_(float v) { return 1.0f / (1.0f + expf(-v)); }
__device__ __forceinline__ float tanh_fast(float x) {
    float y; asm("tanh.approx.f32 %0, %1;" : "=f"(y) : "f"(x)); return y;
}
__device__ __forceinline__ float gelu_fast(float x) {
    float x2 = x * x;
    float inner = 0.7978845608f * x * fmaf(0.044715f, x2, 1.0f);
    float t = tanh_fast(inner);
    float hx = 0.5f * x;
    return fmaf(hx, t, hx);
}
__device__ __forceinline__ unsigned pack_b2(__nv_bfloat16 a, __nv_bfloat16 b) {
    __nv_bfloat162 t = __halves2bfloat162(a, b);
    return *reinterpret_cast<unsigned*>(&t);
}
__device__ __forceinline__ void split2(float a, float b, unsigned& hi, unsigned& lo) {
    __nv_bfloat16 ha = __float2bfloat16(a), hb = __float2bfloat16(b);
    __nv_bfloat16 la = __float2bfloat16(a - __bfloat162float(ha));
    __nv_bfloat16 lb = __float2bfloat16(b - __bfloat162float(hb));
    hi = pack_b2(ha, hb); lo = pack_b2(la, lb);
}

#define MMA16816(c, a0, a1, a2, a3, b0, b1) \
    asm volatile("mma.sync.aligned.m16n8k16.row.col.f32.bf16.bf16.f32 " \
        "{%0,%1,%2,%3}, {%4,%5,%6,%7}, {%8,%9}, {%0,%1,%2,%3};" \
        : "+f"((c)[0]), "+f"((c)[1]), "+f"((c)[2]), "+f"((c)[3]) \
        : "r"(a0), "r"(a1), "r"(a2), "r"(a3), "r"(b0), "r"(b1))

// ============================================================================
// prep_w: W1 (k,n) -> bf16 hi/lo images; Wc1[5:,:] -> bf16 hi image.
// ============================================================================
__global__ void prep_w(const float* __restrict__ W1, const float* __restrict__ Wc1) {
    int idx = blockIdx.x * 256 + threadIdx.x;
    for (int i = idx; i < 32768; i += 4096) {
        int mat = i >> 14;
        int k = (i >> 7) & 127;
        int n = i & 127;
        float v = mat ? Wc1[(5 + k) * 128 + n] : W1[k * 128 + n];
        __nv_bfloat16 hv = __float2bfloat16(v);
        int o = n * 136 + k;
        if (mat) {
            g_B2h[o] = hv;
        } else {
            g_B1h[o] = hv;
            g_B1l[o] = __float2bfloat16(v - __bfloat162float(hv));
        }
    }
}

// ============================================================================
// p1_mma chunk kernel (R9 body): one 128-row tile per CTA. grid = 256 CTAs
// per chunk; CTA b handles batch b, steps [ck*128, (ck+1)*128).
// ============================================================================
#define OFF_AH   0
#define OFF_AL   34816
#define OFF_B1H  69632
#define OFF_B1L  104448
#define OFF_B2H  139264
#define OFF_PAR  174080
#define OFF_SB1  (OFF_PAR + 0)
#define OFF_LNG  (OFF_PAR + 512)
#define OFF_LNB  (OFF_PAR + 1024)
#define OFF_BC1  (OFF_PAR + 1536)
#define OFF_WINN (OFF_PAR + 2048)   // 2560 B
#define SMEM_P1  (OFF_PAR + 4608)   // 178688 B

__global__ void __launch_bounds__(256, 1)
p1_mma(const float* __restrict__ x,    const float* __restrict__ b1,
       const float* __restrict__ ln_g, const float* __restrict__ ln_b,
       const float* __restrict__ Winn, const float* __restrict__ binn,
       const float* __restrict__ bc1,  int ck)
{
    extern __shared__ char sm[];
    const int tid = threadIdx.x;
    const int wid = tid >> 5, lane = tid & 31;
    const int g = lane >> 2, q = lane & 3;
    const int row0 = blockIdx.x * NS + ck * 128;

    uint16_t* pAh = (uint16_t*)(sm + OFF_AH);
    uint16_t* pAl = (uint16_t*)(sm + OFF_AL);
    const uint16_t* pB1h = (const uint16_t*)(sm + OFF_B1H);
    const uint16_t* pB1l = (const uint16_t*)(sm + OFF_B1L);
    const uint16_t* pB2h = (const uint16_t*)(sm + OFF_B2H);

    if (tid < 128) {
        ((float*)(sm + OFF_SB1))[tid] = b1[tid];
        ((float*)(sm + OFF_LNG))[tid] = ln_g[tid];
        ((float*)(sm + OFF_LNB))[tid] = ln_b[tid];
        ((float*)(sm + OFF_BC1))[tid] = bc1[tid];
    }
    for (int i = tid; i < 640; i += 256) ((float*)(sm + OFF_WINN))[i] = Winn[i];
    {
        const uint4* s1h = (const uint4*)g_B1h; const uint4* s1l = (const uint4*)g_B1l;
        const uint4* s2h = (const uint4*)g_B2h;
        uint4* d1h = (uint4*)pB1h; uint4* d1l = (uint4*)pB1l;
        uint4* d2h = (uint4*)pB2h;
        for (int i = tid; i < 2176; i += 256) {
            d1h[i] = s1h[i]; d1l[i] = s1l[i]; d2h[i] = s2h[i];
        }
    }
    {
        const float4* xt = (const float4*)(x + (size_t)row0 * 128);
        for (int i = tid; i < 4096; i += 256) {
            float4 v = xt[i];
            int row = i >> 5, k4 = (i & 31) * 4;
            unsigned h0, l0, h1, l1;
            split2(v.x, v.y, h0, l0);
            split2(v.z, v.w, h1, l1);
            *(uint2*)&pAh[row * 136 + k4] = make_uint2(h0, h1);
            *(uint2*)&pAl[row * 136 + k4] = make_uint2(l0, l1);
        }
    }
    __syncthreads();

    const int rA = wid * 16 + g;
    const int rB = rA + 8;

    // ---- GEMM1: acc = x @ W1 (3-term bf16 split) ----
    float acc[16][4];
#pragma unroll
    for (int nc = 0; nc < 16; nc++)
#pragma unroll
        for (int j = 0; j < 4; j++) acc[nc][j] = 0.f;

#pragma unroll 2
    for (int kc = 0; kc < 8; kc++) {
        const int k0 = kc * 16;
        unsigned ah0 = *(const unsigned*)&pAh[rA * 136 + k0 + 2 * q];
        unsigned ah1 = *(const unsigned*)&pAh[rB * 136 + k0 + 2 * q];
        unsigned ah2 = *(const unsigned*)&pAh[rA * 136 + k0 + 8 + 2 * q];
        unsigned ah3 = *(const unsigned*)&pAh[rB * 136 + k0 + 8 + 2 * q];
        unsigned al0 = *(const unsigned*)&pAl[rA * 136 + k0 + 2 * q];
        unsigned al1 = *(const unsigned*)&pAl[rB * 136 + k0 + 2 * q];
        unsigned al2 = *(const unsigned*)&pAl[rA * 136 + k0 + 8 + 2 * q];
        unsigned al3 = *(const unsigned*)&pAl[rB * 136 + k0 + 8 + 2 * q];
#pragma unroll
        for (int nc = 0; nc < 16; nc++) {
            const int nb = (nc * 8 + g) * 136 + k0 + 2 * q;
            unsigned bh0 = *(const unsigned*)&pB1h[nb];
            unsigned bh1 = *(const unsigned*)&pB1h[nb + 8];
            unsigned bl0 = *(const unsigned*)&pB1l[nb];
            unsigned bl1 = *(const unsigned*)&pB1l[nb + 8];
            MMA16816(acc[nc], ah0, ah1, ah2, ah3, bh0, bh1);
            MMA16816(acc[nc], ah0, ah1, ah2, ah3, bl0, bl1);
            MMA16816(acc[nc], al0, al1, al2, al3, bh0, bh1);
        }
    }

    // ---- Epilogue A ----
    const float* sB1 = (const float*)(sm + OFF_SB1);
    const float* sLG = (const float*)(sm + OFF_LNG);
    const float* sLB = (const float*)(sm + OFF_LNB);
    const float* sWn = (const float*)(sm + OFF_WINN);

    float sumA = 0.f, sqA = 0.f, sumB = 0.f, sqB = 0.f;
#pragma unroll
    for (int nc = 0; nc < 16; nc++) {
        const int c0 = nc * 8 + 2 * q;
        float v0 = acc[nc][0] + sB1[c0], v1 = acc[nc][1] + sB1[c0 + 1];
        float v2 = acc[nc][2] + sB1[c0], v3 = acc[nc][3] + sB1[c0 + 1];
        acc[nc][0] = v0; acc[nc][1] = v1; acc[nc][2] = v2; acc[nc][3] = v3;
        sumA += v0 + v1; sqA = fmaf(v0, v0, fmaf(v1, v1, sqA));
        sumB += v2 + v3; sqB = fmaf(v2, v2, fmaf(v3, v3, sqB));
    }
#pragma unroll
    for (int off = 1; off <= 2; off <<= 1) {
        sumA += __shfl_xor_sync(0xffffffffu, sumA, off);
        sqA  += __shfl_xor_sync(0xffffffffu, sqA,  off);
        sumB += __shfl_xor_sync(0xffffffffu, sumB, off);
        sqB  += __shfl_xor_sync(0xffffffffu, sqB,  off);
    }
    const float muA = sumA * 0.0078125f;
    const float rsA = rsqrtf(sqA * 0.0078125f - muA * muA + 1e-5f);
    const float muB = sumB * 0.0078125f;
    const float rsB = rsqrtf(sqB * 0.0078125f - muB * muB + 1e-5f);

    float bxA[5] = {0, 0, 0, 0, 0}, bxB[5] = {0, 0, 0, 0, 0};
#pragma unroll
    for (int nc = 0; nc < 16; nc++) {
        const int c0 = nc * 8 + 2 * q;
        float h0 = gelu_exact((acc[nc][0] - muA) * rsA * sLG[c0]     + sLB[c0]);
        float h1 = gelu_exact((acc[nc][1] - muA) * rsA * sLG[c0 + 1] + sLB[c0 + 1]);
        float h2 = gelu_exact((acc[nc][2] - muB) * rsB * sLG[c0]     + sLB[c0]);
        float h3 = gelu_exact((acc[nc][3] - muB) * rsB * sLG[c0 + 1] + sLB[c0 + 1]);
        acc[nc][0] = h0; acc[nc][1] = h1; acc[nc][2] = h2; acc[nc][3] = h3;
#pragma unroll
        for (int j = 0; j < 5; j++) {
            bxA[j] = fmaf(h0, sWn[c0 * 5 + j], fmaf(h1, sWn[(c0 + 1) * 5 + j], bxA[j]));
            bxB[j] = fmaf(h2, sWn[c0 * 5 + j], fmaf(h3, sWn[(c0 + 1) * 5 + j], bxB[j]));
        }
    }
#pragma unroll
    for (int off = 1; off <= 2; off <<= 1)
#pragma unroll
        for (int j = 0; j < 5; j++) {
            bxA[j] += __shfl_xor_sync(0xffffffffu, bxA[j], off);
            bxB[j] += __shfl_xor_sync(0xffffffffu, bxB[j], off);
        }
    if (q == 0) {
#pragma unroll
        for (int j = 0; j < 5; j++) {
            float bn = __ldg(&binn[j]);
            g_bx[(size_t)(row0 + rA) * 8 + j] = bxA[j] + bn;
            g_bx[(size_t)(row0 + rB) * 8 + j] = bxB[j] + bn;
        }
    }

    // repack h into GEMM2 A-fragments (hi only — corr_scale-damped path)
    unsigned fh[8][4];
#pragma unroll
    for (int kc = 0; kc < 8; kc++) {
        fh[kc][0] = pack_b2(__float2bfloat16(acc[2*kc][0]),     __float2bfloat16(acc[2*kc][1]));
        fh[kc][1] = pack_b2(__float2bfloat16(acc[2*kc][2]),     __float2bfloat16(acc[2*kc][3]));
        fh[kc][2] = pack_b2(__float2bfloat16(acc[2*kc + 1][0]), __float2bfloat16(acc[2*kc + 1][1]));
        fh[kc][3] = pack_b2(__float2bfloat16(acc[2*kc + 1][2]), __float2bfloat16(acc[2*kc + 1][3]));
    }

    // ---- GEMM2: acc = h @ Wc1[5:,:]  (single-term bf16) ----
#pragma unroll
    for (int nc = 0; nc < 16; nc++)
#pragma unroll
        for (int j = 0; j < 4; j++) acc[nc][j] = 0.f;

#pragma unroll 2
    for (int kc = 0; kc < 8; kc++) {
        const int k0 = kc * 16;
#pragma unroll
        for (int nc = 0; nc < 16; nc++) {
            const int nb = (nc * 8 + g) * 136 + k0 + 2 * q;
            unsigned bh0 = *(const unsigned*)&pB2h[nb];
            unsigned bh1 = *(const unsigned*)&pB2h[nb + 8];
            MMA16816(acc[nc], fh[kc][0], fh[kc][1], fh[kc][2], fh[kc][3], bh0, bh1);
        }
    }

    // ---- Epilogue B: +bc1 -> g_u ----
    const float* sBC = (const float*)(sm + OFF_BC1);
    const size_t gra = (size_t)(row0 + rA) * 128;
    const size_t grb = (size_t)(row0 + rB) * 128;
#pragma unroll
    for (int nc = 0; nc < 16; nc++) {
        const int c0 = nc * 8 + 2 * q;
        float bA = sBC[c0], bB = sBC[c0 + 1];
        *(float2*)&g_u[gra + c0] = make_float2(acc[nc][0] + bA, acc[nc][1] + bB);
        *(float2*)&g_u[grb + c0] = make_float2(acc[nc][2] + bA, acc[nc][3] + bB);
    }
}

// ============================================================================
// p2 chunk kernel (R9 body, 128 steps per launch). 128 blocks x 64 threads
// (2 warps, one batch each) — small CTAs co-schedule beside p1's big CTAs.
// State persisted in g_state between chunk launches.
// ============================================================================
__global__ void __launch_bounds__(64)
p2_chunk(const float* __restrict__ Wc1, const float* __restrict__ Wc2,
         const float* __restrict__ bc2, const float* __restrict__ corr_scale,
         const float* __restrict__ raw_aL, const float* __restrict__ raw_aT,
         const float* __restrict__ raw_g,  const float* __restrict__ raw_aR,
         const float* __restrict__ omega,  float* __restrict__ out, int ck)
{
    const int warp = threadIdx.x >> 5, lane = threadIdx.x & 31;
    const int b = blockIdx.x * 2 + warp;

    const float aL = sigmoidf_(raw_aL[0]) * 0.15f + 0.85f;
    const float aT = sigmoidf_(raw_aT[0]) * 0.25f + 0.70f;
    const float gg = sigmoidf_(raw_g[0])  * 0.20f + 0.80f;
    const float aR = sigmoidf_(raw_aR[0]) * 0.40f;
    const float om = omega[0];
    const float gc = gg * cosf(om), gs = gg * sinf(om), ngs = -gs;
    const float cs = corr_scale[0];

    const int c0 = lane * 4;
    float Ws[5][4], Wo[4][5], bb[5];
#pragma unroll
    for (int i = 0; i < 5; i++)
#pragma unroll
        for (int c = 0; c < 4; c++) Ws[i][c] = Wc1[i*128 + c0 + c];
#pragma unroll
    for (int c = 0; c < 4; c++)
#pragma unroll
        for (int k = 0; k < 5; k++) Wo[c][k] = Wc2[(c0 + c)*5 + k];
#pragma unroll
    for (int k = 0; k < 5; k++) bb[k] = bc2[k];

    float s0, s1, s2, s3, s4;
    if (ck == 0) {
        s0 = s1 = s2 = s3 = s4 = 0.f;
    } else {
        s0 = g_state[b*5+0]; s1 = g_state[b*5+1]; s2 = g_state[b*5+2];
        s3 = g_state[b*5+3]; s4 = g_state[b*5+4];
    }

    const float4* up  = (const float4*)(g_u + (size_t)b * NS * 128);
    const float*  bxp = g_bx + (size_t)b * NS * 8;
    const int tbase = ck * 128;

    float4 ub[4], xb[4]; float x4b[4];
#pragma unroll
    for (int j = 0; j < 4; j++) {
        ub[j]  = up[(tbase + j) * 32 + lane];
        xb[j]  = *(const float4*)(bxp + (tbase + j) * 8);
        x4b[j] = bxp[(tbase + j) * 8 + 4];
    }

    for (int t0 = tbase; t0 < tbase + 128; t0 += 4) {
#pragma unroll
        for (int j = 0; j < 4; j++) {
            const int t = t0 + j;
            const float4 u = ub[j];
            const float4 x = xb[j];
            const float  x4 = x4b[j];
            ub[j]  = up[(t + 4) * 32 + lane];
            xb[j]  = *(const float4*)(bxp + (t + 4) * 8);
            x4b[j] = bxp[(t + 4) * 8 + 4];

            float l0 = fmaf(s0, aL, x.x);
            float l1 = fmaf(s1, aT, x.y);
            float l2 = fmaf(s2, gc, fmaf(s3, gs,  x.z));
            float l3 = fmaf(s3, gc, fmaf(s2, ngs, x.w));
            float l4 = fmaf(s4, aR, x4);

            float a0 = u.x, a1 = u.y, a2 = u.z, a3 = u.w;
            a0 = fmaf(l0, Ws[0][0], a0); a1 = fmaf(l0, Ws[0][1], a1);
            a2 = fmaf(l0, Ws[0][2], a2); a3 = fmaf(l0, Ws[0][3], a3);
            a0 = fmaf(l1, Ws[1][0], a0); a1 = fmaf(l1, Ws[1][1], a1);
            a2 = fmaf(l1, Ws[1][2], a2); a3 = fmaf(l1, Ws[1][3], a3);
            a0 = fmaf(l2, Ws[2][0], a0); a1 = fmaf(l2, Ws[2][1], a1);
            a2 = fmaf(l2, Ws[2][2], a2); a3 = fmaf(l2, Ws[2][3], a3);
            a0 = fmaf(l3, Ws[3][0], a0); a1 = fmaf(l3, Ws[3][1], a1);
            a2 = fmaf(l3, Ws[3][2], a2); a3 = fmaf(l3, Ws[3][3], a3);
            a0 = fmaf(l4, Ws[4][0], a0); a1 = fmaf(l4, Ws[4][1], a1);
            a2 = fmaf(l4, Ws[4][2], a2); a3 = fmaf(l4, Ws[4][3], a3);

            float m0 = gelu_fast(a0);
            float m1 = gelu_fast(a1);
            float m2 = gelu_fast(a2);
            float m3 = gelu_fast(a3);

            float p0 = m0*Wo[0][0], p1 = m0*Wo[0][1], p2 = m0*Wo[0][2],
                  p3 = m0*Wo[0][3], p4 = m0*Wo[0][4];
            p0 = fmaf(m1, Wo[1][0], p0); p1 = fmaf(m1, Wo[1][1], p1);
            p2 = fmaf(m1, Wo[1][2], p2); p3 = fmaf(m1, Wo[1][3], p3);
            p4 = fmaf(m1, Wo[1][4], p4);
            p0 = fmaf(m2, Wo[2][0], p0); p1 = fmaf(m2, Wo[2][1], p1);
            p2 = fmaf(m2, Wo[2][2], p2); p3 = fmaf(m2, Wo[2][3], p3);
            p4 = fmaf(m2, Wo[2][4], p4);
            p0 = fmaf(m3, Wo[3][0], p0); p1 = fmaf(m3, Wo[3][1], p1);
            p2 = fmaf(m3, Wo[3][2], p2); p3 = fmaf(m3, Wo[3][3], p3);
            p4 = fmaf(m3, Wo[3][4], p4);

#pragma unroll
            for (int off = 16; off; off >>= 1) {
                p0 += __shfl_xor_sync(0xffffffffu, p0, off);
                p1 += __shfl_xor_sync(0xffffffffu, p1, off);
                p2 += __shfl_xor_sync(0xffffffffu, p2, off);
                p3 += __shfl_xor_sync(0xffffffffu, p3, off);
                p4 += __shfl_xor_sync(0xffffffffu, p4, off);
            }
            s0 = fmaf(cs, tanh_fast(p0 + bb[0]), l0);
            s1 = fmaf(cs, tanh_fast(p1 + bb[1]), l1);
            s2 = fmaf(cs, tanh_fast(p2 + bb[2]), l2);
            s3 = fmaf(cs, tanh_fast(p3 + bb[3]), l3);
            s4 = fmaf(cs, tanh_fast(p4 + bb[4]), l4);
        }
    }

    if (lane == 0) {
        if (ck == 7) {
            out[b*5+0] = s0; out[b*5+1] = s1; out[b*5+2] = s2;
            out[b*5+3] = s3; out[b*5+4] = s4;
        } else {
            g_state[b*5+0] = s0; g_state[b*5+1] = s1; g_state[b*5+2] = s2;
            g_state[b*5+3] = s3; g_state[b*5+4] = s4;
        }
    }
}

// ============================================================================
extern "C" void kernel_launch(void* const* d_in, const int* in_sizes, int n_in,
                              void* d_out, int out_size)
{
    (void)in_sizes; (void)n_in; (void)out_size;
    const float* x    = (const float*)d_in[0];
    const float* W1   = (const float*)d_in[1];
    const float* b1   = (const float*)d_in[2];
    const float* ln_g = (const float*)d_in[3];
    const float* ln_b = (const float*)d_in[4];
    const float* Winn = (const float*)d_in[5];
    const float* binn = (const float*)d_in[6];
    const float* Wc1  = (const float*)d_in[7];
    const float* bc1  = (const float*)d_in[8];
    const float* Wc2  = (const float*)d_in[9];
    const float* bc2  = (const float*)d_in[10];
    const float* cscl = (const float*)d_in[11];
    const float* raL  = (const float*)d_in[12];
    const float* raT  = (const float*)d_in[13];
    const float* rg   = (const float*)d_in[14];
    const float* raR  = (const float*)d_in[15];
    const float* om   = (const float*)d_in[16];

    static int init_done = 0;
    static cudaStream_t s_side;
    static cudaEvent_t evP1[8], evJoin;
    if (!init_done) {
        cudaFuncSetAttribute(p1_mma, cudaFuncAttributeMaxDynamicSharedMemorySize, SMEM_P1);
        cudaStreamCreateWithFlags(&s_side, cudaStreamNonBlocking);
        for (int k = 0; k < 8; k++)
            cudaEventCreateWithFlags(&evP1[k], cudaEventDisableTiming);
        cudaEventCreateWithFlags(&evJoin, cudaEventDisableTiming);
        init_done = 1;
    }

    // main (capture-origin) stream: prep + 8 producer chunks
    prep_w<<<16, 256>>>(W1, Wc1);
    for (int k = 0; k < 8; k++) {
        p1_mma<<<NB, 256, SMEM_P1>>>(x, b1, ln_g, ln_b, Winn, binn, bc1, k);
        cudaEventRecord(evP1[k], 0);
    }
    // side stream: 8 consumer chunks, each gated on its producer chunk
    for (int k = 0; k < 8; k++) {
        cudaStreamWaitEvent(s_side, evP1[k], 0);
        p2_chunk<<<NB / 2, 64, 0, s_side>>>(Wc1, Wc2, bc2, cscl, raL, raT, rg, raR, om,
                                            (float*)d_out, k);
    }
    // join side stream back into the origin stream
    cudaEventRecord(evJoin, s_side);
    cudaStreamWaitEvent(0, evJoin, 0);
}

// round 14
// speedup vs baseline: 8.3914x; 1.0548x over previous
#include <cuda_runtime.h>
#include <cuda_bf16.h>
#include <math.h>
#include <stdint.h>

// Problem constants
#define NB   256
#define NS   1024
#define NROWS (NB * NS)   // 262144
#define NCHUNK 16
#define CSTEP  64         // steps per chunk

// Scratch (device globals; padded for branch-free depth-4 prefetch)
__device__ float g_u[(size_t)NROWS * 128 + 512];
__device__ float g_bx[(size_t)NROWS * 8 + 32];
__device__ float g_state[NB * 5];
// bf16 weight images, transposed to [n][k], row stride 136 elements
__device__ __nv_bfloat16 g_B1h[17408], g_B1l[17408], g_B2h[17408];

// ---------------- math helpers ----------------
__device__ __forceinline__ float gelu_exact(float x) {
    return 0.5f * x * (1.0f + erff(x * 0.7071067811865475f));
}
__device__ __forceinline__ float sigmoidf_(float v) { return 1.0f / (1.0f + expf(-v)); }
__device__ __forceinline__ float tanh_fast(float x) {
    float y; asm("tanh.approx.f32 %0, %1;" : "=f"(y) : "f"(x)); return y;
}
__device__ __forceinline__ float gelu_fast(float x) {
    float x2 = x * x;
    float inner = 0.7978845608f * x * fmaf(0.044715f, x2, 1.0f);
    float t = tanh_fast(inner);
    float hx = 0.5f * x;
    return fmaf(hx, t, hx);
}
__device__ __forceinline__ unsigned pack_b2(__nv_bfloat16 a, __nv_bfloat16 b) {
    __nv_bfloat162 t = __halves2bfloat162(a, b);
    return *reinterpret_cast<unsigned*>(&t);
}
__device__ __forceinline__ void split2(float a, float b, unsigned& hi, unsigned& lo) {
    __nv_bfloat16 ha = __float2bfloat16(a), hb = __float2bfloat16(b);
    __nv_bfloat16 la = __float2bfloat16(a - __bfloat162float(ha));
    __nv_bfloat16 lb = __float2bfloat16(b - __bfloat162float(hb));
    hi = pack_b2(ha, hb); lo = pack_b2(la, lb);
}

#define MMA16816(c, a0, a1, a2, a3, b0, b1) \
    asm volatile("mma.sync.aligned.m16n8k16.row.col.f32.bf16.bf16.f32 " \
        "{%0,%1,%2,%3}, {%4,%5,%6,%7}, {%8,%9}, {%0,%1,%2,%3};" \
        : "+f"((c)[0]), "+f"((c)[1]), "+f"((c)[2]), "+f"((c)[3]) \
        : "r"(a0), "r"(a1), "r"(a2), "r"(a3), "r"(b0), "r"(b1))

// ============================================================================
// prep_w: W1 (k,n) -> bf16 hi/lo images; Wc1[5:,:] -> bf16 hi image.
// ============================================================================
__global__ void prep_w(const float* __restrict__ W1, const float* __restrict__ Wc1) {
    int idx = blockIdx.x * 256 + threadIdx.x;
    for (int i = idx; i < 32768; i += 4096) {
        int mat = i >> 14;
        int k = (i >> 7) & 127;
        int n = i & 127;
        float v = mat ? Wc1[(5 + k) * 128 + n] : W1[k * 128 + n];
        __nv_bfloat16 hv = __float2bfloat16(v);
        int o = n * 136 + k;
        if (mat) {
            g_B2h[o] = hv;
        } else {
            g_B1h[o] = hv;
            g_B1l[o] = __float2bfloat16(v - __bfloat162float(hv));
        }
    }
}

// ============================================================================
// p1_mma chunk kernel (R9 body). 128 CTAs per chunk (one wave, leaving SMs
// free for concurrent p2). One CTA = 128 rows = TWO batches' 64-step
// segments: tile row r -> batch (2*blk + (r>>6)), step ck*64 + (r&63).
// ============================================================================
#define OFF_AH   0
#define OFF_AL   34816
#define OFF_B1H  69632
#define OFF_B1L  104448
#define OFF_B2H  139264
#define OFF_PAR  174080
#define OFF_SB1  (OFF_PAR + 0)
#define OFF_LNG  (OFF_PAR + 512)
#define OFF_LNB  (OFF_PAR + 1024)
#define OFF_BC1  (OFF_PAR + 1536)
#define OFF_WINN (OFF_PAR + 2048)   // 2560 B
#define SMEM_P1  (OFF_PAR + 4608)   // 178688 B

__global__ void __launch_bounds__(256, 1)
p1_mma(const float* __restrict__ x,    const float* __restrict__ b1,
       const float* __restrict__ ln_g, const float* __restrict__ ln_b,
       const float* __restrict__ Winn, const float* __restrict__ binn,
       const float* __restrict__ bc1,  int ck)
{
    extern __shared__ char sm[];
    const int tid = threadIdx.x;
    const int wid = tid >> 5, lane = tid & 31;
    const int g = lane >> 2, q = lane & 3;
    const int b0 = blockIdx.x * 2;
    const int t0c = ck * CSTEP;
    // row -> global row mapping: grow(r) = (b0 + (r>>6))*NS + t0c + (r&63)
    const size_t base0 = (size_t)b0 * NS + t0c;          // rows 0..63
    const size_t base1 = (size_t)(b0 + 1) * NS + t0c;    // rows 64..127

    uint16_t* pAh = (uint16_t*)(sm + OFF_AH);
    uint16_t* pAl = (uint16_t*)(sm + OFF_AL);
    const uint16_t* pB1h = (const uint16_t*)(sm + OFF_B1H);
    const uint16_t* pB1l = (const uint16_t*)(sm + OFF_B1L);
    const uint16_t* pB2h = (const uint16_t*)(sm + OFF_B2H);

    if (tid < 128) {
        ((float*)(sm + OFF_SB1))[tid] = b1[tid];
        ((float*)(sm + OFF_LNG))[tid] = ln_g[tid];
        ((float*)(sm + OFF_LNB))[tid] = ln_b[tid];
        ((float*)(sm + OFF_BC1))[tid] = bc1[tid];
    }
    for (int i = tid; i < 640; i += 256) ((float*)(sm + OFF_WINN))[i] = Winn[i];
    {
        const uint4* s1h = (const uint4*)g_B1h; const uint4* s1l = (const uint4*)g_B1l;
        const uint4* s2h = (const uint4*)g_B2h;
        uint4* d1h = (uint4*)pB1h; uint4* d1l = (uint4*)pB1l;
        uint4* d2h = (uint4*)pB2h;
        for (int i = tid; i < 2176; i += 256) {
            d1h[i] = s1h[i]; d1l[i] = s1l[i]; d2h[i] = s2h[i];
        }
    }
    {
        const float4* xt = (const float4*)x;
        for (int i = tid; i < 4096; i += 256) {
            int row = i >> 5, c4 = i & 31;
            size_t grow = (row < 64 ? base0 : base1) + (row & 63);
            float4 v = xt[grow * 32 + c4];
            int k4 = c4 * 4;
            unsigned h0, l0, h1, l1;
            split2(v.x, v.y, h0, l0);
            split2(v.z, v.w, h1, l1);
            *(uint2*)&pAh[row * 136 + k4] = make_uint2(h0, h1);
            *(uint2*)&pAl[row * 136 + k4] = make_uint2(l0, l1);
        }
    }
    __syncthreads();

    const int rA = wid * 16 + g;
    const int rB = rA + 8;
    const size_t growA = (rA < 64 ? base0 : base1) + (rA & 63);
    const size_t growB = (rB < 64 ? base0 : base1) + (rB & 63);

    // ---- GEMM1: acc = x @ W1 (3-term bf16 split) ----
    float acc[16][4];
#pragma unroll
    for (int nc = 0; nc < 16; nc++)
#pragma unroll
        for (int j = 0; j < 4; j++) acc[nc][j] = 0.f;

#pragma unroll 2
    for (int kc = 0; kc < 8; kc++) {
        const int k0 = kc * 16;
        unsigned ah0 = *(const unsigned*)&pAh[rA * 136 + k0 + 2 * q];
        unsigned ah1 = *(const unsigned*)&pAh[rB * 136 + k0 + 2 * q];
        unsigned ah2 = *(const unsigned*)&pAh[rA * 136 + k0 + 8 + 2 * q];
        unsigned ah3 = *(const unsigned*)&pAh[rB * 136 + k0 + 8 + 2 * q];
        unsigned al0 = *(const unsigned*)&pAl[rA * 136 + k0 + 2 * q];
        unsigned al1 = *(const unsigned*)&pAl[rB * 136 + k0 + 2 * q];
        unsigned al2 = *(const unsigned*)&pAl[rA * 136 + k0 + 8 + 2 * q];
        unsigned al3 = *(const unsigned*)&pAl[rB * 136 + k0 + 8 + 2 * q];
#pragma unroll
        for (int nc = 0; nc < 16; nc++) {
            const int nb = (nc * 8 + g) * 136 + k0 + 2 * q;
            unsigned bh0 = *(const unsigned*)&pB1h[nb];
            unsigned bh1 = *(const unsigned*)&pB1h[nb + 8];
            unsigned bl0 = *(const unsigned*)&pB1l[nb];
            unsigned bl1 = *(const unsigned*)&pB1l[nb + 8];
            MMA16816(acc[nc], ah0, ah1, ah2, ah3, bh0, bh1);
            MMA16816(acc[nc], ah0, ah1, ah2, ah3, bl0, bl1);
            MMA16816(acc[nc], al0, al1, al2, al3, bh0, bh1);
        }
    }

    // ---- Epilogue A ----
    const float* sB1 = (const float*)(sm + OFF_SB1);
    const float* sLG = (const float*)(sm + OFF_LNG);
    const float* sLB = (const float*)(sm + OFF_LNB);
    const float* sWn = (const float*)(sm + OFF_WINN);

    float sumA = 0.f, sqA = 0.f, sumB = 0.f, sqB = 0.f;
#pragma unroll
    for (int nc = 0; nc < 16; nc++) {
        const int c0 = nc * 8 + 2 * q;
        float v0 = acc[nc][0] + sB1[c0], v1 = acc[nc][1] + sB1[c0 + 1];
        float v2 = acc[nc][2] + sB1[c0], v3 = acc[nc][3] + sB1[c0 + 1];
        acc[nc][0] = v0; acc[nc][1] = v1; acc[nc][2] = v2; acc[nc][3] = v3;
        sumA += v0 + v1; sqA = fmaf(v0, v0, fmaf(v1, v1, sqA));
        sumB += v2 + v3; sqB = fmaf(v2, v2, fmaf(v3, v3, sqB));
    }
#pragma unroll
    for (int off = 1; off <= 2; off <<= 1) {
        sumA += __shfl_xor_sync(0xffffffffu, sumA, off);
        sqA  += __shfl_xor_sync(0xffffffffu, sqA,  off);
        sumB += __shfl_xor_sync(0xffffffffu, sumB, off);
        sqB  += __shfl_xor_sync(0xffffffffu, sqB,  off);
    }
    const float muA = sumA * 0.0078125f;
    const float rsA = rsqrtf(sqA * 0.0078125f - muA * muA + 1e-5f);
    const float muB = sumB * 0.0078125f;
    const float rsB = rsqrtf(sqB * 0.0078125f - muB * muB + 1e-5f);

    float bxA[5] = {0, 0, 0, 0, 0}, bxB[5] = {0, 0, 0, 0, 0};
#pragma unroll
    for (int nc = 0; nc < 16; nc++) {
        const int c0 = nc * 8 + 2 * q;
        float h0 = gelu_exact((acc[nc][0] - muA) * rsA * sLG[c0]     + sLB[c0]);
        float h1 = gelu_exact((acc[nc][1] - muA) * rsA * sLG[c0 + 1] + sLB[c0 + 1]);
        float h2 = gelu_exact((acc[nc][2] - muB) * rsB * sLG[c0]     + sLB[c0]);
        float h3 = gelu_exact((acc[nc][3] - muB) * rsB * sLG[c0 + 1] + sLB[c0 + 1]);
        acc[nc][0] = h0; acc[nc][1] = h1; acc[nc][2] = h2; acc[nc][3] = h3;
#pragma unroll
        for (int j = 0; j < 5; j++) {
            bxA[j] = fmaf(h0, sWn[c0 * 5 + j], fmaf(h1, sWn[(c0 + 1) * 5 + j], bxA[j]));
            bxB[j] = fmaf(h2, sWn[c0 * 5 + j], fmaf(h3, sWn[(c0 + 1) * 5 + j], bxB[j]));
        }
    }
#pragma unroll
    for (int off = 1; off <= 2; off <<= 1)
#pragma unroll
        for (int j = 0; j < 5; j++) {
            bxA[j] += __shfl_xor_sync(0xffffffffu, bxA[j], off);
            bxB[j] += __shfl_xor_sync(0xffffffffu, bxB[j], off);
        }
    if (q == 0) {
#pragma unroll
        for (int j = 0; j < 5; j++) {
            float bn = __ldg(&binn[j]);
            g_bx[growA * 8 + j] = bxA[j] + bn;
            g_bx[growB * 8 + j] = bxB[j] + bn;
        }
    }

    // repack h into GEMM2 A-fragments (hi only — corr_scale-damped path)
    unsigned fh[8][4];
#pragma unroll
    for (int kc = 0; kc < 8; kc++) {
        fh[kc][0] = pack_b2(__float2bfloat16(acc[2*kc][0]),     __float2bfloat16(acc[2*kc][1]));
        fh[kc][1] = pack_b2(__float2bfloat16(acc[2*kc][2]),     __float2bfloat16(acc[2*kc][3]));
        fh[kc][2] = pack_b2(__float2bfloat16(acc[2*kc + 1][0]), __float2bfloat16(acc[2*kc + 1][1]));
        fh[kc][3] = pack_b2(__float2bfloat16(acc[2*kc + 1][2]), __float2bfloat16(acc[2*kc + 1][3]));
    }

    // ---- GEMM2: acc = h @ Wc1[5:,:]  (single-term bf16) ----
#pragma unroll
    for (int nc = 0; nc < 16; nc++)
#pragma unroll
        for (int j = 0; j < 4; j++) acc[nc][j] = 0.f;

#pragma unroll 2
    for (int kc = 0; kc < 8; kc++) {
        const int k0 = kc * 16;
#pragma unroll
        for (int nc = 0; nc < 16; nc++) {
            const int nb = (nc * 8 + g) * 136 + k0 + 2 * q;
            unsigned bh0 = *(const unsigned*)&pB2h[nb];
            unsigned bh1 = *(const unsigned*)&pB2h[nb + 8];
            MMA16816(acc[nc], fh[kc][0], fh[kc][1], fh[kc][2], fh[kc][3], bh0, bh1);
        }
    }

    // ---- Epilogue B: +bc1 -> g_u ----
    const float* sBC = (const float*)(sm + OFF_BC1);
    const size_t gra = growA * 128;
    const size_t grb = growB * 128;
#pragma unroll
    for (int nc = 0; nc < 16; nc++) {
        const int c0 = nc * 8 + 2 * q;
        float bA = sBC[c0], bB = sBC[c0 + 1];
        *(float2*)&g_u[gra + c0] = make_float2(acc[nc][0] + bA, acc[nc][1] + bB);
        *(float2*)&g_u[grb + c0] = make_float2(acc[nc][2] + bA, acc[nc][3] + bB);
    }
}

// ============================================================================
// p2 chunk kernel (R9 body, CSTEP steps per launch). 128 blocks x 64 threads
// (2 warps, one batch each). State persisted in g_state between launches.
// ============================================================================
__global__ void __launch_bounds__(64)
p2_chunk(const float* __restrict__ Wc1, const float* __restrict__ Wc2,
         const float* __restrict__ bc2, const float* __restrict__ corr_scale,
         const float* __restrict__ raw_aL, const float* __restrict__ raw_aT,
         const float* __restrict__ raw_g,  const float* __restrict__ raw_aR,
         const float* __restrict__ omega,  float* __restrict__ out, int ck)
{
    const int warp = threadIdx.x >> 5, lane = threadIdx.x & 31;
    const int b = blockIdx.x * 2 + warp;

    const float aL = sigmoidf_(raw_aL[0]) * 0.15f + 0.85f;
    const float aT = sigmoidf_(raw_aT[0]) * 0.25f + 0.70f;
    const float gg = sigmoidf_(raw_g[0])  * 0.20f + 0.80f;
    const float aR = sigmoidf_(raw_aR[0]) * 0.40f;
    const float om = omega[0];
    const float gc = gg * cosf(om), gs = gg * sinf(om), ngs = -gs;
    const float cs = corr_scale[0];

    const int c0 = lane * 4;
    float Ws[5][4], Wo[4][5], bb[5];
#pragma unroll
    for (int i = 0; i < 5; i++)
#pragma unroll
        for (int c = 0; c < 4; c++) Ws[i][c] = Wc1[i*128 + c0 + c];
#pragma unroll
    for (int c = 0; c < 4; c++)
#pragma unroll
        for (int k = 0; k < 5; k++) Wo[c][k] = Wc2[(c0 + c)*5 + k];
#pragma unroll
    for (int k = 0; k < 5; k++) bb[k] = bc2[k];

    float s0, s1, s2, s3, s4;
    if (ck == 0) {
        s0 = s1 = s2 = s3 = s4 = 0.f;
    } else {
        s0 = g_state[b*5+0]; s1 = g_state[b*5+1]; s2 = g_state[b*5+2];
        s3 = g_state[b*5+3]; s4 = g_state[b*5+4];
    }

    const float4* up  = (const float4*)(g_u + (size_t)b * NS * 128);
    const float*  bxp = g_bx + (size_t)b * NS * 8;
    const int tbase = ck * CSTEP;

    float4 ub[4], xb[4]; float x4b[4];
#pragma unroll
    for (int j = 0; j < 4; j++) {
        ub[j]  = up[(tbase + j) * 32 + lane];
        xb[j]  = *(const float4*)(bxp + (tbase + j) * 8);
        x4b[j] = bxp[(tbase + j) * 8 + 4];
    }

    for (int t0 = tbase; t0 < tbase + CSTEP; t0 += 4) {
#pragma unroll
        for (int j = 0; j < 4; j++) {
            const int t = t0 + j;
            const float4 u = ub[j];
            const float4 x = xb[j];
            const float  x4 = x4b[j];
            ub[j]  = up[(t + 4) * 32 + lane];
            xb[j]  = *(const float4*)(bxp + (t + 4) * 8);
            x4b[j] = bxp[(t + 4) * 8 + 4];

            float l0 = fmaf(s0, aL, x.x);
            float l1 = fmaf(s1, aT, x.y);
            float l2 = fmaf(s2, gc, fmaf(s3, gs,  x.z));
            float l3 = fmaf(s3, gc, fmaf(s2, ngs, x.w));
            float l4 = fmaf(s4, aR, x4);

            float a0 = u.x, a1 = u.y, a2 = u.z, a3 = u.w;
            a0 = fmaf(l0, Ws[0][0], a0); a1 = fmaf(l0, Ws[0][1], a1);
            a2 = fmaf(l0, Ws[0][2], a2); a3 = fmaf(l0, Ws[0][3], a3);
            a0 = fmaf(l1, Ws[1][0], a0); a1 = fmaf(l1, Ws[1][1], a1);
            a2 = fmaf(l1, Ws[1][2], a2); a3 = fmaf(l1, Ws[1][3], a3);
            a0 = fmaf(l2, Ws[2][0], a0); a1 = fmaf(l2, Ws[2][1], a1);
            a2 = fmaf(l2, Ws[2][2], a2); a3 = fmaf(l2, Ws[2][3], a3);
            a0 = fmaf(l3, Ws[3][0], a0); a1 = fmaf(l3, Ws[3][1], a1);
            a2 = fmaf(l3, Ws[3][2], a2); a3 = fmaf(l3, Ws[3][3], a3);
            a0 = fmaf(l4, Ws[4][0], a0); a1 = fmaf(l4, Ws[4][1], a1);
            a2 = fmaf(l4, Ws[4][2], a2); a3 = fmaf(l4, Ws[4][3], a3);

            float m0 = gelu_fast(a0);
            float m1 = gelu_fast(a1);
            float m2 = gelu_fast(a2);
            float m3 = gelu_fast(a3);

            float p0 = m0*Wo[0][0], p1 = m0*Wo[0][1], p2 = m0*Wo[0][2],
                  p3 = m0*Wo[0][3], p4 = m0*Wo[0][4];
            p0 = fmaf(m1, Wo[1][0], p0); p1 = fmaf(m1, Wo[1][1], p1);
            p2 = fmaf(m1, Wo[1][2], p2); p3 = fmaf(m1, Wo[1][3], p3);
            p4 = fmaf(m1, Wo[1][4], p4);
            p0 = fmaf(m2, Wo[2][0], p0); p1 = fmaf(m2, Wo[2][1], p1);
            p2 = fmaf(m2, Wo[2][2], p2); p3 = fmaf(m2, Wo[2][3], p3);
            p4 = fmaf(m2, Wo[2][4], p4);
            p0 = fmaf(m3, Wo[3][0], p0); p1 = fmaf(m3, Wo[3][1], p1);
            p2 = fmaf(m3, Wo[3][2], p2); p3 = fmaf(m3, Wo[3][3], p3);
            p4 = fmaf(m3, Wo[3][4], p4);

#pragma unroll
            for (int off = 16; off; off >>= 1) {
                p0 += __shfl_xor_sync(0xffffffffu, p0, off);
                p1 += __shfl_xor_sync(0xffffffffu, p1, off);
                p2 += __shfl_xor_sync(0xffffffffu, p2, off);
                p3 += __shfl_xor_sync(0xffffffffu, p3, off);
                p4 += __shfl_xor_sync(0xffffffffu, p4, off);
            }
            s0 = fmaf(cs, tanh_fast(p0 + bb[0]), l0);
            s1 = fmaf(cs, tanh_fast(p1 + bb[1]), l1);
            s2 = fmaf(cs, tanh_fast(p2 + bb[2]), l2);
            s3 = fmaf(cs, tanh_fast(p3 + bb[3]), l3);
            s4 = fmaf(cs, tanh_fast(p4 + bb[4]), l4);
        }
    }

    if (lane == 0) {
        if (ck == NCHUNK - 1) {
            out[b*5+0] = s0; out[b*5+1] = s1; out[b*5+2] = s2;
            out[b*5+3] = s3; out[b*5+4] = s4;
        } else {
            g_state[b*5+0] = s0; g_state[b*5+1] = s1; g_state[b*5+2] = s2;
            g_state[b*5+3] = s3; g_state[b*5+4] = s4;
        }
    }
}

// ============================================================================
extern "C" void kernel_launch(void* const* d_in, const int* in_sizes, int n_in,
                              void* d_out, int out_size)
{
    (void)in_sizes; (void)n_in; (void)out_size;
    const float* x    = (const float*)d_in[0];
    const float* W1   = (const float*)d_in[1];
    const float* b1   = (const float*)d_in[2];
    const float* ln_g = (const float*)d_in[3];
    const float* ln_b = (const float*)d_in[4];
    const float* Winn = (const float*)d_in[5];
    const float* binn = (const float*)d_in[6];
    const float* Wc1  = (const float*)d_in[7];
    const float* bc1  = (const float*)d_in[8];
    const float* Wc2  = (const float*)d_in[9];
    const float* bc2  = (const float*)d_in[10];
    const float* cscl = (const float*)d_in[11];
    const float* raL  = (const float*)d_in[12];
    const float* raT  = (const float*)d_in[13];
    const float* rg   = (const float*)d_in[14];
    const float* raR  = (const float*)d_in[15];
    const float* om   = (const float*)d_in[16];

    static int init_done = 0;
    static cudaStream_t s_side;
    static cudaEvent_t evP1[NCHUNK], evJoin;
    if (!init_done) {
        cudaFuncSetAttribute(p1_mma, cudaFuncAttributeMaxDynamicSharedMemorySize, SMEM_P1);
        cudaStreamCreateWithFlags(&s_side, cudaStreamNonBlocking);
        for (int k = 0; k < NCHUNK; k++)
            cudaEventCreateWithFlags(&evP1[k], cudaEventDisableTiming);
        cudaEventCreateWithFlags(&evJoin, cudaEventDisableTiming);
        init_done = 1;
    }

    // main (capture-origin) stream: prep + producer chunks (128 CTAs each)
    prep_w<<<16, 256>>>(W1, Wc1);
    for (int k = 0; k < NCHUNK; k++) {
        p1_mma<<<NB / 2, 256, SMEM_P1>>>(x, b1, ln_g, ln_b, Winn, binn, bc1, k);
        cudaEventRecord(evP1[k], 0);
    }
    // side stream: consumer chunks, each gated on its producer chunk
    for (int k = 0; k < NCHUNK; k++) {
        cudaStreamWaitEvent(s_side, evP1[k], 0);
        p2_chunk<<<NB / 2, 64, 0, s_side>>>(Wc1, Wc2, bc2, cscl, raL, raT, rg, raR, om,
                                            (float*)d_out, k);
    }
    // join side stream back into the origin stream
    cudaEventRecord(evJoin, s_side);
    cudaStreamWaitEvent(0, evJoin, 0);
}